// round 1
// baseline (speedup 1.0000x reference)
#include <cuda_runtime.h>
#include <math.h>

// Problem constants (fixed shapes from reference)
#define NQ      262144      // total queries = B*L*cg = 4*1024*64
#define NSAM    1024        // prior samples
#define NPAIR   512         // sample pairs (f32x2 packing)
#define TSTRIDE 20          // floats per pair row in smem table (80 B, 16B-aligned rows)
#define THREADS 448
#define ZHAT_OFF   0
#define NOQ_OFF    1048576  // B*L*C
#define IDX_OFF    2097152  // 2*B*L*C
#define FULL_OUT   2359296  // + B*L*cg

// ---- packed f32x2 helpers (Blackwell FFMA2) ----
__device__ __forceinline__ unsigned long long ffma2(unsigned long long a,
                                                    unsigned long long b,
                                                    unsigned long long c) {
    unsigned long long d;
    asm("fma.rn.f32x2 %0, %1, %2, %3;" : "=l"(d) : "l"(a), "l"(b), "l"(c));
    return d;
}
__device__ __forceinline__ unsigned long long pack2(float x) {
    unsigned long long r;
    asm("mov.b64 %0, {%1, %1};" : "=l"(r) : "f"(x));
    return r;
}
__device__ __forceinline__ float lo2(unsigned long long a) {
    return __uint_as_float((unsigned)(a & 0xffffffffull));
}
__device__ __forceinline__ float hi2(unsigned long long a) {
    return __uint_as_float((unsigned)(a >> 32));
}

__global__ void __launch_bounds__(THREADS, 1)
gq_kernel(const float* __restrict__ z,
          const float* __restrict__ eps,
          const float* __restrict__ prior,
          float* __restrict__ out,
          int out_size)
{
    // Packed sample table: per pair p (= samples 2p, 2p+1), 9 f32x2 words:
    //   [c | S_g0 | S_g1 | S_g2 | S_g3 | T_g0 | T_g1 | T_g2 | T_g3]  (T = -0.5*S^2)
    // c_n = 0.5 * sum_g S^2  (the -beta*nlp_sum term, constants dropped)
    __shared__ __align__(16) float tab[NPAIR * TSTRIDE];   // 40960 B

    const int tid = threadIdx.x;
    for (int n = tid; n < NSAM; n += THREADS) {
        float4 s = reinterpret_cast<const float4*>(prior)[n];
        int p = n >> 1, h = n & 1;
        float* t = &tab[p * TSTRIDE];
        t[0 + h]  = 0.5f * (s.x*s.x + s.y*s.y + s.z*s.z + s.w*s.w);
        t[2 + h]  = s.x;  t[4 + h]  = s.y;  t[6 + h]  = s.z;  t[8 + h]  = s.w;
        t[10 + h] = -0.5f * s.x * s.x;
        t[12 + h] = -0.5f * s.y * s.y;
        t[14 + h] = -0.5f * s.z * s.z;
        t[16 + h] = -0.5f * s.w * s.w;
        // t[18], t[19] pad
    }

    // Each thread owns 4 consecutive queries k0..k0+3 (j%4==0, never crosses a row)
    const int gtid = blockIdx.x * THREADS + tid;
    const int k0   = gtid * 4;
    const bool valid = (k0 < NQ);
    const int bl = k0 >> 6;     // (b*L + l)
    const int j  = k0 & 63;

    // Packed per-query coefficients: uu[q][g] = (u,u), vv[q][g] = (v,v)
    unsigned long long uu[4][4], vv[4][4];
    #pragma unroll
    for (int q = 0; q < 4; q++)
        #pragma unroll
        for (int g = 0; g < 4; g++) { uu[q][g] = 0ull; vv[q][g] = 0ull; }

    if (valid) {
        #pragma unroll
        for (int g = 0; g < 4; g++) {
            const int moff = bl * 512 + g * 64 + j;           // mu
            float4 mu4 = *reinterpret_cast<const float4*>(z + moff);
            float4 lv4 = *reinterpret_cast<const float4*>(z + moff + 256);
            lv4.x = fminf(fmaxf(lv4.x, -30.0f), 20.0f);
            lv4.y = fminf(fmaxf(lv4.y, -30.0f), 20.0f);
            lv4.z = fminf(fmaxf(lv4.z, -30.0f), 20.0f);
            lv4.w = fminf(fmaxf(lv4.w, -30.0f), 20.0f);
            float ivx = expf(-lv4.x), ivy = expf(-lv4.y);
            float ivz = expf(-lv4.z), ivw = expf(-lv4.w);
            uu[0][g] = pack2(mu4.x * ivx);  vv[0][g] = pack2(ivx);
            uu[1][g] = pack2(mu4.y * ivy);  vv[1][g] = pack2(ivy);
            uu[2][g] = pack2(mu4.z * ivz);  vv[2][g] = pack2(ivz);
            uu[3][g] = pack2(mu4.w * ivw);  vv[3][g] = pack2(ivw);

            // Fused zhat_noquant = mu + eps * exp(0.5*logvar)
            const int eoff = bl * 256 + g * 64 + j;
            float4 e4 = *reinterpret_cast<const float4*>(eps + eoff);
            float4 nq;
            nq.x = fmaf(e4.x, expf(0.5f * lv4.x), mu4.x);
            nq.y = fmaf(e4.y, expf(0.5f * lv4.y), mu4.y);
            nq.z = fmaf(e4.z, expf(0.5f * lv4.z), mu4.z);
            nq.w = fmaf(e4.w, expf(0.5f * lv4.w), mu4.w);
            if (out_size >= IDX_OFF)
                *reinterpret_cast<float4*>(out + NOQ_OFF + eoff) = nq;
        }
    }
    __syncthreads();

    // Running argmax, separate even/odd sample streams (index resolved at end).
    // Strict '>' updates preserve jnp.argmax first-max tie semantics.
    const float NEG_INF = -__int_as_float(0x7f800000);
    float be[4], bo[4];
    int   pe[4], po[4];
    #pragma unroll
    for (int q = 0; q < 4; q++) { be[q] = NEG_INF; bo[q] = NEG_INF; pe[q] = 0; po[q] = 0; }

    #pragma unroll 2
    for (int p = 0; p < NPAIR; p++) {
        const float* base = &tab[p * TSTRIDE];
        ulonglong2 w01 = *reinterpret_cast<const ulonglong2*>(base + 0);   // c, S_g0
        ulonglong2 w23 = *reinterpret_cast<const ulonglong2*>(base + 4);   // S_g1, S_g2
        ulonglong2 w45 = *reinterpret_cast<const ulonglong2*>(base + 8);   // S_g3, T_g0
        ulonglong2 w67 = *reinterpret_cast<const ulonglong2*>(base + 12);  // T_g1, T_g2
        unsigned long long w8 = *reinterpret_cast<const unsigned long long*>(base + 16); // T_g3

        #pragma unroll
        for (int q = 0; q < 4; q++) {
            unsigned long long acc = w01.x;                // init with c pair
            acc = ffma2(uu[q][0], w01.y, acc);
            acc = ffma2(uu[q][1], w23.x, acc);
            acc = ffma2(uu[q][2], w23.y, acc);
            acc = ffma2(uu[q][3], w45.x, acc);
            acc = ffma2(vv[q][0], w45.y, acc);
            acc = ffma2(vv[q][1], w67.x, acc);
            acc = ffma2(vv[q][2], w67.y, acc);
            acc = ffma2(vv[q][3], w8,    acc);
            float s0 = lo2(acc), s1 = hi2(acc);
            if (s0 > be[q]) { be[q] = s0; pe[q] = p; }
            if (s1 > bo[q]) { bo[q] = s1; po[q] = p; }
        }
    }

    if (valid) {
        int bidx[4];
        #pragma unroll
        for (int q = 0; q < 4; q++) {
            int ie = 2 * pe[q];
            int io = 2 * po[q] + 1;
            if      (bo[q] > be[q]) bidx[q] = io;
            else if (be[q] > bo[q]) bidx[q] = ie;
            else                    bidx[q] = min(ie, io);   // exact tie: first index
        }

        // Gather winning prior rows (prior table is L2-hot, 16 KB)
        float r[4][4];
        #pragma unroll
        for (int q = 0; q < 4; q++) {
            float4 s = reinterpret_cast<const float4*>(prior)[bidx[q]];
            r[q][0] = s.x; r[q][1] = s.y; r[q][2] = s.z; r[q][3] = s.w;
        }
        #pragma unroll
        for (int g = 0; g < 4; g++) {
            float4 o4 = make_float4(r[0][g], r[1][g], r[2][g], r[3][g]);
            *reinterpret_cast<float4*>(out + ZHAT_OFF + bl * 256 + g * 64 + j) = o4;
        }
        if (out_size >= FULL_OUT) {
            float4 i4 = make_float4((float)bidx[0], (float)bidx[1],
                                    (float)bidx[2], (float)bidx[3]);
            *reinterpret_cast<float4*>(out + IDX_OFF + k0) = i4;
        }
    }
}

extern "C" void kernel_launch(void* const* d_in, const int* in_sizes, int n_in,
                              void* d_out, int out_size) {
    const float* z     = (const float*)d_in[0];
    const float* eps   = (const float*)d_in[1];
    const float* prior = (const float*)d_in[2];
    (void)in_sizes; (void)n_in;
    const int thread_slots = NQ / 4;                       // 65536
    const int blocks = (thread_slots + THREADS - 1) / THREADS;  // 147 -> one wave
    gq_kernel<<<blocks, THREADS>>>(z, eps, prior, (float*)d_out, out_size);
}

// round 2
// speedup vs baseline: 1.1007x; 1.1007x over previous
#include <cuda_runtime.h>
#include <math.h>

// Problem constants (fixed shapes from reference)
#define NQ      262144      // total queries = B*L*cg = 4*1024*64
#define NSAM    1024        // prior samples
#define NPAIR   512         // sample pairs (f32x2 packing)
#define TSTRIDE 20          // floats per pair row in smem table (80 B, 16B-aligned rows)
#define THREADS 448
#define QPT     2           // queries per thread
#define ZHAT_OFF   0
#define NOQ_OFF    1048576  // B*L*C
#define IDX_OFF    2097152  // 2*B*L*C
#define FULL_OUT   2359296  // + B*L*cg

// ---- packed f32x2 helpers (Blackwell FFMA2) ----
__device__ __forceinline__ unsigned long long ffma2(unsigned long long a,
                                                    unsigned long long b,
                                                    unsigned long long c) {
    unsigned long long d;
    asm("fma.rn.f32x2 %0, %1, %2, %3;" : "=l"(d) : "l"(a), "l"(b), "l"(c));
    return d;
}
__device__ __forceinline__ unsigned long long pack2(float x) {
    unsigned long long r;
    asm("mov.b64 %0, {%1, %1};" : "=l"(r) : "f"(x));
    return r;
}
__device__ __forceinline__ float lo2(unsigned long long a) {
    return __uint_as_float((unsigned)(a & 0xffffffffull));
}
__device__ __forceinline__ float hi2(unsigned long long a) {
    return __uint_as_float((unsigned)(a >> 32));
}

__global__ void __launch_bounds__(THREADS, 2)
gq_kernel(const float* __restrict__ z,
          const float* __restrict__ eps,
          const float* __restrict__ prior,
          float* __restrict__ out,
          int out_size)
{
    // Packed sample table: per pair p (= samples 2p, 2p+1), 9 f32x2 words:
    //   [c | S_g0 | S_g1 | S_g2 | S_g3 | T_g0 | T_g1 | T_g2 | T_g3]  (T = -0.5*S^2)
    // c_n = 0.5 * sum_g S^2  (the -beta*nlp_sum term; query/global constants dropped)
    __shared__ __align__(16) float tab[NPAIR * TSTRIDE];   // 40960 B per CTA, 2 CTAs/SM

    const int tid = threadIdx.x;
    for (int n = tid; n < NSAM; n += THREADS) {
        float4 s = reinterpret_cast<const float4*>(prior)[n];
        int p = n >> 1, h = n & 1;
        float* t = &tab[p * TSTRIDE];
        t[0 + h]  = 0.5f * (s.x*s.x + s.y*s.y + s.z*s.z + s.w*s.w);
        t[2 + h]  = s.x;  t[4 + h]  = s.y;  t[6 + h]  = s.z;  t[8 + h]  = s.w;
        t[10 + h] = -0.5f * s.x * s.x;
        t[12 + h] = -0.5f * s.y * s.y;
        t[14 + h] = -0.5f * s.z * s.z;
        t[16 + h] = -0.5f * s.w * s.w;
        // t[18], t[19] pad
    }

    // Each thread owns 2 consecutive queries k0, k0+1 (j even, never crosses a row)
    const int gtid = blockIdx.x * THREADS + tid;
    const int k0   = gtid * QPT;
    const bool valid = (k0 < NQ);
    const int bl = k0 >> 6;     // (b*L + l)
    const int j  = k0 & 63;

    // Packed per-query coefficients: uu[q][g] = (u,u), vv[q][g] = (v,v)
    unsigned long long uu[QPT][4], vv[QPT][4];

    if (valid) {
        #pragma unroll
        for (int g = 0; g < 4; g++) {
            const int moff = bl * 512 + g * 64 + j;           // mu
            float2 mu2 = *reinterpret_cast<const float2*>(z + moff);
            float2 lv2 = *reinterpret_cast<const float2*>(z + moff + 256);
            lv2.x = fminf(fmaxf(lv2.x, -30.0f), 20.0f);
            lv2.y = fminf(fmaxf(lv2.y, -30.0f), 20.0f);
            float ivx = expf(-lv2.x), ivy = expf(-lv2.y);
            uu[0][g] = pack2(mu2.x * ivx);  vv[0][g] = pack2(ivx);
            uu[1][g] = pack2(mu2.y * ivy);  vv[1][g] = pack2(ivy);

            // Fused zhat_noquant = mu + eps * exp(0.5*logvar)
            const int eoff = bl * 256 + g * 64 + j;
            float2 e2 = *reinterpret_cast<const float2*>(eps + eoff);
            float2 nq;
            nq.x = fmaf(e2.x, expf(0.5f * lv2.x), mu2.x);
            nq.y = fmaf(e2.y, expf(0.5f * lv2.y), mu2.y);
            if (out_size >= IDX_OFF)
                *reinterpret_cast<float2*>(out + NOQ_OFF + eoff) = nq;
        }
    }
    __syncthreads();
    if (!valid) return;   // tail threads exit (no further barriers)

    // Running argmax, separate even/odd sample streams (index resolved at end).
    // Strict '>' updates preserve jnp.argmax first-max tie semantics.
    const float NEG_INF = -__int_as_float(0x7f800000);
    float be[QPT], bo[QPT];
    int   pe[QPT], po[QPT];
    #pragma unroll
    for (int q = 0; q < QPT; q++) { be[q] = NEG_INF; bo[q] = NEG_INF; pe[q] = 0; po[q] = 0; }

    #pragma unroll 2
    for (int p = 0; p < NPAIR; p++) {
        const float* base = &tab[p * TSTRIDE];
        ulonglong2 w01 = *reinterpret_cast<const ulonglong2*>(base + 0);   // c, S_g0
        ulonglong2 w23 = *reinterpret_cast<const ulonglong2*>(base + 4);   // S_g1, S_g2
        ulonglong2 w45 = *reinterpret_cast<const ulonglong2*>(base + 8);   // S_g3, T_g0
        ulonglong2 w67 = *reinterpret_cast<const ulonglong2*>(base + 12);  // T_g1, T_g2
        unsigned long long w8 = *reinterpret_cast<const unsigned long long*>(base + 16); // T_g3

        #pragma unroll
        for (int q = 0; q < QPT; q++) {
            unsigned long long acc = w01.x;                // init with c pair
            acc = ffma2(uu[q][0], w01.y, acc);
            acc = ffma2(uu[q][1], w23.x, acc);
            acc = ffma2(uu[q][2], w23.y, acc);
            acc = ffma2(uu[q][3], w45.x, acc);
            acc = ffma2(vv[q][0], w45.y, acc);
            acc = ffma2(vv[q][1], w67.x, acc);
            acc = ffma2(vv[q][2], w67.y, acc);
            acc = ffma2(vv[q][3], w8,    acc);
            float s0 = lo2(acc), s1 = hi2(acc);
            if (s0 > be[q]) { be[q] = s0; pe[q] = p; }
            if (s1 > bo[q]) { bo[q] = s1; po[q] = p; }
        }
    }

    {
        int bidx[QPT];
        #pragma unroll
        for (int q = 0; q < QPT; q++) {
            int ie = 2 * pe[q];
            int io = 2 * po[q] + 1;
            if      (bo[q] > be[q]) bidx[q] = io;
            else if (be[q] > bo[q]) bidx[q] = ie;
            else                    bidx[q] = min(ie, io);   // exact tie: first index
        }

        // Gather winning prior rows (prior table is L2-hot, 16 KB)
        float r[QPT][4];
        #pragma unroll
        for (int q = 0; q < QPT; q++) {
            float4 s = reinterpret_cast<const float4*>(prior)[bidx[q]];
            r[q][0] = s.x; r[q][1] = s.y; r[q][2] = s.z; r[q][3] = s.w;
        }
        #pragma unroll
        for (int g = 0; g < 4; g++) {
            float2 o2 = make_float2(r[0][g], r[1][g]);
            *reinterpret_cast<float2*>(out + ZHAT_OFF + bl * 256 + g * 64 + j) = o2;
        }
        if (out_size >= FULL_OUT) {
            float2 i2 = make_float2((float)bidx[0], (float)bidx[1]);
            *reinterpret_cast<float2*>(out + IDX_OFF + k0) = i2;
        }
    }
}

extern "C" void kernel_launch(void* const* d_in, const int* in_sizes, int n_in,
                              void* d_out, int out_size) {
    const float* z     = (const float*)d_in[0];
    const float* eps   = (const float*)d_in[1];
    const float* prior = (const float*)d_in[2];
    (void)in_sizes; (void)n_in;
    const int thread_slots = NQ / QPT;                         // 131072
    const int blocks = (thread_slots + THREADS - 1) / THREADS; // 293 -> 2 CTAs/SM, one wave
    gq_kernel<<<blocks, THREADS>>>(z, eps, prior, (float*)d_out, out_size);
}